// round 1
// baseline (speedup 1.0000x reference)
#include <cuda_runtime.h>
#include <cuda_bf16.h>
#include <math.h>

// Problem constants
#define B_ROWS   16384
#define D_EMB    128
#define D_HID    1024
#define D_FEAT   4096
#define KSPLIT   8              // j-chunks for the W2 GEMV split-K
#define JCHUNK   (D_HID / KSPLIT)   // 128

// Scratch (no allocations allowed)
__device__ float g_hidden[2][D_HID];           // relu(ctx @ W1 + b1)
__device__ float g_part[2][KSPLIT][D_FEAT];    // split-K partials
__device__ float g_gate[2][D_FEAT];            // final gates (2*sigmoid)

// ---------------------------------------------------------------------------
// K1: hidden = relu(ctx[1,128] @ W1[128,1024] + b1)
// grid: (2 gates) blocks, 1024 threads. Coalesced across j (W1 row-major).
// ---------------------------------------------------------------------------
__global__ void gate_hidden_kernel(const float* __restrict__ ctx1,
                                   const float* __restrict__ W1_1,
                                   const float* __restrict__ b1_1,
                                   const float* __restrict__ ctx2,
                                   const float* __restrict__ W1_2,
                                   const float* __restrict__ b1_2) {
    const int g = blockIdx.x;           // gate index 0/1
    const int j = threadIdx.x;          // hidden unit
    const float* ctx = (g == 0) ? ctx1 : ctx2;
    const float* W1  = (g == 0) ? W1_1 : W1_2;
    const float* b1  = (g == 0) ? b1_1 : b1_2;

    __shared__ float s_ctx[D_EMB];
    if (j < D_EMB) s_ctx[j] = ctx[j];
    __syncthreads();

    float acc = b1[j];
    #pragma unroll 8
    for (int k = 0; k < D_EMB; ++k) {
        acc = fmaf(s_ctx[k], W1[k * D_HID + j], acc);
    }
    g_hidden[g][j] = fmaxf(acc, 0.0f);
}

// ---------------------------------------------------------------------------
// K2: split-K partials of hidden[1024] @ W2[1024,4096]
// grid: (D_FEAT/128, KSPLIT, 2), block 128 threads.
// Each warp reads 128B contiguous rows of W2 — fully coalesced; 32 MB total.
// ---------------------------------------------------------------------------
__global__ void gate_partial_kernel(const float* __restrict__ W2_1,
                                    const float* __restrict__ W2_2) {
    const int g  = blockIdx.z;
    const int jc = blockIdx.y;
    const int f  = blockIdx.x * blockDim.x + threadIdx.x;   // 0..4095
    const float* W2 = (g == 0) ? W2_1 : W2_2;

    const int j0 = jc * JCHUNK;
    // stage the 128 hidden values for this chunk in shared (broadcast reads)
    __shared__ float s_h[JCHUNK];
    if (threadIdx.x < JCHUNK) s_h[threadIdx.x] = g_hidden[g][j0 + threadIdx.x];
    __syncthreads();

    float acc = 0.0f;
    const float* w = W2 + (size_t)j0 * D_FEAT + f;
    #pragma unroll 8
    for (int j = 0; j < JCHUNK; ++j) {
        acc = fmaf(s_h[j], w[(size_t)j * D_FEAT], acc);
    }
    g_part[g][jc][f] = acc;
}

// ---------------------------------------------------------------------------
// K3: reduce partials, add b2, sigmoid * 2 -> g_gate
// grid: (D_FEAT/256, 2), block 256
// ---------------------------------------------------------------------------
__global__ void gate_finish_kernel(const float* __restrict__ b2_1,
                                   const float* __restrict__ b2_2) {
    const int g = blockIdx.y;
    const int f = blockIdx.x * blockDim.x + threadIdx.x;
    const float* b2 = (g == 0) ? b2_1 : b2_2;

    float acc = b2[f];
    #pragma unroll
    for (int c = 0; c < KSPLIT; ++c) acc += g_part[g][c][f];
    // 2 * sigmoid(acc)
    g_gate[g][f] = 2.0f / (1.0f + __expf(-acc));
}

// ---------------------------------------------------------------------------
// K4: streaming elementwise — float4 per thread, write both outputs.
// 768 MB of HBM traffic; this launch dominates runtime.
// ---------------------------------------------------------------------------
__global__ void scale_kernel(const float4* __restrict__ emb4,
                             float4* __restrict__ out4,
                             long long n4) {
    const long long idx = (long long)blockIdx.x * blockDim.x + threadIdx.x;
    if (idx >= n4) return;

    const int fc = (int)(idx & (D_FEAT / 4 - 1));   // float4 column within row
    const float4 e  = emb4[idx];
    const float4 g1 = reinterpret_cast<const float4*>(g_gate[0])[fc];
    const float4 g2 = reinterpret_cast<const float4*>(g_gate[1])[fc];

    float4 o1, o2;
    o1.x = e.x * g1.x; o1.y = e.y * g1.y; o1.z = e.z * g1.z; o1.w = e.w * g1.w;
    o2.x = e.x * g2.x; o2.y = e.y * g2.y; o2.z = e.z * g2.z; o2.w = e.w * g2.w;

    out4[idx]      = o1;
    out4[n4 + idx] = o2;
}

// ---------------------------------------------------------------------------
// Launch
// Inputs (metadata order):
//  0 flat_emb [B, D_FEAT]
//  1 fs1_ctx_bias [1, D_EMB]
//  2 fs2_ctx_bias [1, D_EMB]
//  3 fs1_W1 [D_EMB, D_HID]   4 fs1_b1 [D_HID]
//  5 fs1_W2 [D_HID, D_FEAT]  6 fs1_b2 [D_FEAT]
//  7 fs2_W1 [D_EMB, D_HID]   8 fs2_b1 [D_HID]
//  9 fs2_W2 [D_HID, D_FEAT] 10 fs2_b2 [D_FEAT]
// Output: concat(feature1, feature2) fp32, 2*B*D_FEAT elements.
// ---------------------------------------------------------------------------
extern "C" void kernel_launch(void* const* d_in, const int* in_sizes, int n_in,
                              void* d_out, int out_size) {
    const float* flat_emb = (const float*)d_in[0];
    const float* c1  = (const float*)d_in[1];
    const float* c2  = (const float*)d_in[2];
    const float* W1a = (const float*)d_in[3];
    const float* b1a = (const float*)d_in[4];
    const float* W2a = (const float*)d_in[5];
    const float* b2a = (const float*)d_in[6];
    const float* W1b = (const float*)d_in[7];
    const float* b1b = (const float*)d_in[8];
    const float* W2b = (const float*)d_in[9];
    const float* b2b = (const float*)d_in[10];

    float* out = (float*)d_out;

    // K1: hidden layer (2 blocks x 1024 threads)
    gate_hidden_kernel<<<2, D_HID>>>(c1, W1a, b1a, c2, W1b, b1b);

    // K2: split-K W2 GEMV partials
    {
        dim3 grid(D_FEAT / 128, KSPLIT, 2);
        gate_partial_kernel<<<grid, 128>>>(W2a, W2b);
    }

    // K3: reduce + sigmoid
    {
        dim3 grid(D_FEAT / 256, 2);
        gate_finish_kernel<<<grid, 256>>>(b2a, b2b);
    }

    // K4: streaming multiply
    {
        const long long n4 = (long long)B_ROWS * (D_FEAT / 4);   // 16,777,216
        const int threads = 256;
        const long long blocks = (n4 + threads - 1) / threads;   // 65536
        scale_kernel<<<(unsigned)blocks, threads>>>(
            (const float4*)flat_emb, (float4*)out, n4);
    }
}

// round 2
// speedup vs baseline: 1.0060x; 1.0060x over previous
#include <cuda_runtime.h>
#include <cuda_bf16.h>
#include <math.h>

// Problem constants
#define B_ROWS   16384
#define D_EMB    128
#define D_HID    1024
#define D_FEAT   4096
#define KSPLIT1  4               // k-chunks for the W1 GEMV split-K
#define KCHUNK1  (D_EMB / KSPLIT1)    // 32
#define KSPLIT2  16              // j-chunks for the W2 GEMV split-K
#define JCHUNK2  (D_HID / KSPLIT2)    // 64

// Scratch (device globals; fully overwritten every replay -> deterministic)
__device__ float g_hid_part[2][KSPLIT1][D_HID];   // W1 split-K partials (pre-bias, pre-relu)
__device__ float g_part[2][KSPLIT2][D_FEAT];      // W2 split-K partials
__device__ float g_gate[2][D_FEAT];               // final gates (2*sigmoid)

// ---------------------------------------------------------------------------
// K1: split-K partials of ctx[128] @ W1[128,1024]  (float4 over j)
// grid: (KSPLIT1, 2), block 256. Each thread owns one float4 column group.
// ---------------------------------------------------------------------------
__global__ void gate_hidden_kernel(const float* __restrict__ ctx1,
                                   const float* __restrict__ W1_1,
                                   const float* __restrict__ ctx2,
                                   const float* __restrict__ W1_2) {
    const int kc = blockIdx.x;               // k-chunk
    const int g  = blockIdx.y;               // gate index
    const int j4 = threadIdx.x;              // float4 column 0..255
    const float* ctx = (g == 0) ? ctx1 : ctx2;
    const float4* W14 = (const float4*)((g == 0) ? W1_1 : W1_2);

    __shared__ float s_ctx[KCHUNK1];
    if (j4 < KCHUNK1) s_ctx[j4] = ctx[kc * KCHUNK1 + j4];
    __syncthreads();

    float4 acc = make_float4(0.f, 0.f, 0.f, 0.f);
    const int k0 = kc * KCHUNK1;
    #pragma unroll 8
    for (int k = 0; k < KCHUNK1; ++k) {
        const float c = s_ctx[k];
        const float4 w = W14[(size_t)(k0 + k) * (D_HID / 4) + j4];
        acc.x = fmaf(c, w.x, acc.x);
        acc.y = fmaf(c, w.y, acc.y);
        acc.z = fmaf(c, w.z, acc.z);
        acc.w = fmaf(c, w.w, acc.w);
    }
    ((float4*)g_hid_part[g][kc])[j4] = acc;
}

// ---------------------------------------------------------------------------
// K2: split-K partials of hidden[1024] @ W2[1024,4096]  (float4 over f)
// grid: (D_FEAT/4/128, KSPLIT2, 2) = (8,16,2) = 256 blocks, 128 threads.
// Prologue reduces W1 partials + bias + relu for this chunk's 64 hidden vals.
// ---------------------------------------------------------------------------
__global__ void gate_partial_kernel(const float* __restrict__ W2_1,
                                    const float* __restrict__ b1_1,
                                    const float* __restrict__ W2_2,
                                    const float* __restrict__ b1_2) {
    const int g  = blockIdx.z;
    const int jc = blockIdx.y;
    const int f4 = blockIdx.x * blockDim.x + threadIdx.x;   // 0..1023
    const float4* W24 = (const float4*)((g == 0) ? W2_1 : W2_2);
    const float*  b1  = (g == 0) ? b1_1 : b1_2;

    const int j0 = jc * JCHUNK2;
    __shared__ float s_h[JCHUNK2];
    if (threadIdx.x < JCHUNK2) {
        const int j = j0 + threadIdx.x;
        float h = b1[j];
        #pragma unroll
        for (int c = 0; c < KSPLIT1; ++c) h += g_hid_part[g][c][j];
        s_h[threadIdx.x] = fmaxf(h, 0.0f);
    }
    __syncthreads();

    float4 acc = make_float4(0.f, 0.f, 0.f, 0.f);
    const float4* w = W24 + (size_t)j0 * (D_FEAT / 4) + f4;
    #pragma unroll 8
    for (int j = 0; j < JCHUNK2; ++j) {
        const float h = s_h[j];
        const float4 wv = w[(size_t)j * (D_FEAT / 4)];
        acc.x = fmaf(h, wv.x, acc.x);
        acc.y = fmaf(h, wv.y, acc.y);
        acc.z = fmaf(h, wv.z, acc.z);
        acc.w = fmaf(h, wv.w, acc.w);
    }
    ((float4*)g_part[g][jc])[f4] = acc;
}

// ---------------------------------------------------------------------------
// K3: reduce partials + b2, 2*sigmoid -> g_gate  (float4)
// grid: (D_FEAT/4/256, 2) = (4,2), block 256
// ---------------------------------------------------------------------------
__global__ void gate_finish_kernel(const float* __restrict__ b2_1,
                                   const float* __restrict__ b2_2) {
    const int g  = blockIdx.y;
    const int f4 = blockIdx.x * blockDim.x + threadIdx.x;   // 0..1023
    const float4* b24 = (const float4*)((g == 0) ? b2_1 : b2_2);

    float4 acc = b24[f4];
    #pragma unroll
    for (int c = 0; c < KSPLIT2; ++c) {
        const float4 p = ((const float4*)g_part[g][c])[f4];
        acc.x += p.x; acc.y += p.y; acc.z += p.z; acc.w += p.w;
    }
    float4 gt;
    gt.x = 2.0f / (1.0f + __expf(-acc.x));
    gt.y = 2.0f / (1.0f + __expf(-acc.y));
    gt.z = 2.0f / (1.0f + __expf(-acc.z));
    gt.w = 2.0f / (1.0f + __expf(-acc.w));
    ((float4*)g_gate[g])[f4] = gt;
}

// ---------------------------------------------------------------------------
// K4: streaming elementwise — 4 float4s per thread (front-batched MLP),
// streaming load/store hints (no reuse of emb or outputs).
// grid: n4/1024 = 16384 blocks, 256 threads. n4 divisible by 1024 -> no guard.
// ---------------------------------------------------------------------------
__global__ void scale_kernel(const float4* __restrict__ emb4,
                             float4* __restrict__ out4,
                             long long n4) {
    const int t = threadIdx.x;
    const long long base = (long long)blockIdx.x * 1024 + t;
    const float4* __restrict__ gate0 = (const float4*)g_gate[0];
    const float4* __restrict__ gate1 = (const float4*)g_gate[1];

    float4 e[4];
    long long idx[4];
    #pragma unroll
    for (int k = 0; k < 4; ++k) {
        idx[k] = base + (long long)k * 256;
        e[k] = __ldcs(&emb4[idx[k]]);
    }
    #pragma unroll
    for (int k = 0; k < 4; ++k) {
        const int fc = (int)(idx[k] & (D_FEAT / 4 - 1));
        const float4 g1 = __ldg(&gate0[fc]);
        const float4 g2 = __ldg(&gate1[fc]);
        float4 o1, o2;
        o1.x = e[k].x * g1.x; o1.y = e[k].y * g1.y;
        o1.z = e[k].z * g1.z; o1.w = e[k].w * g1.w;
        o2.x = e[k].x * g2.x; o2.y = e[k].y * g2.y;
        o2.z = e[k].z * g2.z; o2.w = e[k].w * g2.w;
        __stcs(&out4[idx[k]], o1);
        __stcs(&out4[n4 + idx[k]], o2);
    }
}

// ---------------------------------------------------------------------------
// Launch
// Inputs (metadata order):
//  0 flat_emb [B, D_FEAT]
//  1 fs1_ctx_bias [1, D_EMB]   2 fs2_ctx_bias [1, D_EMB]
//  3 fs1_W1 [128,1024]  4 fs1_b1 [1024]  5 fs1_W2 [1024,4096]  6 fs1_b2 [4096]
//  7 fs2_W1 [128,1024]  8 fs2_b1 [1024]  9 fs2_W2 [1024,4096] 10 fs2_b2 [4096]
// Output: concat(feature1, feature2) fp32, 2*B*D_FEAT elements.
// ---------------------------------------------------------------------------
extern "C" void kernel_launch(void* const* d_in, const int* in_sizes, int n_in,
                              void* d_out, int out_size) {
    const float* flat_emb = (const float*)d_in[0];
    const float* c1  = (const float*)d_in[1];
    const float* c2  = (const float*)d_in[2];
    const float* W1a = (const float*)d_in[3];
    const float* b1a = (const float*)d_in[4];
    const float* W2a = (const float*)d_in[5];
    const float* b2a = (const float*)d_in[6];
    const float* W1b = (const float*)d_in[7];
    const float* b1b = (const float*)d_in[8];
    const float* W2b = (const float*)d_in[9];
    const float* b2b = (const float*)d_in[10];

    float* out = (float*)d_out;

    // K1: W1 GEMV split-K partials
    {
        dim3 grid(KSPLIT1, 2);
        gate_hidden_kernel<<<grid, 256>>>(c1, W1a, c2, W1b);
    }

    // K2: W2 GEMV split-K partials (with fused hidden reduce+relu)
    {
        dim3 grid(D_FEAT / 4 / 128, KSPLIT2, 2);
        gate_partial_kernel<<<grid, 128>>>(W2a, b1a, W2b, b1b);
    }

    // K3: reduce + sigmoid
    {
        dim3 grid(D_FEAT / 4 / 256, 2);
        gate_finish_kernel<<<grid, 256>>>(b2a, b2b);
    }

    // K4: streaming multiply (dominant launch)
    {
        const long long n4 = (long long)B_ROWS * (D_FEAT / 4);   // 16,777,216
        scale_kernel<<<(unsigned)(n4 / 1024), 256>>>(
            (const float4*)flat_emb, (float4*)out, n4);
    }
}